// round 1
// baseline (speedup 1.0000x reference)
#include <cuda_runtime.h>
#include <cstdint>

// ---------------- problem constants ----------------
#define CAMN  4
#define CPC   16      // channels per camera
#define FC    64      // CAMN*CPC = conv channels (in = out)
#define HI    128
#define WI    128
#define ZD    32
#define YD    128
#define XD    256
// padded volume dims (1 halo each side)
#define PZ    34
#define PY    130
#define PX    258
#define PLANE ((size_t)PZ * PY * PX)       // 1,140,360
#define NC_ELEMS (ZD * YD * XD)            // 1,048,576 elements per channel
#define EPSBN 1e-5f

// ---------------- device scratch (zero-initialized at load; pad stays 0) ----
__device__ float g_volp[FC * PZ * PY * PX + 32];   // ~292 MB, tf32-rounded values
__device__ float g_featsT[CAMN * HI * WI * CPC];   // [cam][y][x][c]
__device__ float g_wt[27 * FC * FC];               // [(dz*3+dy)*3+dx][oc][ic], tf32-rounded
__device__ float g_sum[FC];
__device__ float g_sq[FC];
__device__ float g_scale[FC];
__device__ float g_shift[FC];

// ---------------- helpers ----------------
__device__ __forceinline__ float to_tf32(float x) {
    uint32_t u;
    asm("cvt.rna.tf32.f32 %0, %1;" : "=r"(u) : "f"(x));
    return __uint_as_float(u);
}

__device__ __forceinline__ void mma_tf32(float (&c)[4],
                                         uint32_t a0, uint32_t a1, uint32_t a2, uint32_t a3,
                                         uint32_t b0, uint32_t b1) {
    asm volatile(
        "mma.sync.aligned.m16n8k8.row.col.f32.tf32.tf32.f32 "
        "{%0,%1,%2,%3}, {%4,%5,%6,%7}, {%8,%9}, {%0,%1,%2,%3};\n"
        : "+f"(c[0]), "+f"(c[1]), "+f"(c[2]), "+f"(c[3])
        : "r"(a0), "r"(a1), "r"(a2), "r"(a3), "r"(b0), "r"(b1));
}

// ---------------- kernel 1: weight transpose + tf32 round + stat zero ------
// g_wt[koff][oc][ic] <- conv_w[oc][ic][dz][dy][dx], koff = dz*9+dy*3+dx
__global__ void prep_kernel(const float* __restrict__ conv_w) {
    int idx = blockIdx.x * blockDim.x + threadIdx.x;   // 0 .. 27*4096-1
    if (idx < FC) { g_sum[idx] = 0.f; g_sq[idx] = 0.f; }
    if (idx >= 27 * FC * FC) return;
    int koff = idx >> 12;          // /4096
    int rem  = idx & 4095;
    int oc = rem >> 6;
    int ic = rem & 63;
    g_wt[idx] = to_tf32(conv_w[(oc * 64 + ic) * 27 + koff]);
}

// ---------------- kernel 2: feats transpose -> [cam][y][x][c] --------------
__global__ void transpose_kernel(const float* __restrict__ feats) {
    int idx = blockIdx.x * blockDim.x + threadIdx.x;   // 0 .. 1,048,576-1
    if (idx >= CAMN * CPC * HI * WI) return;
    int xw  = idx & (WI - 1);
    int yh  = (idx >> 7) & (HI - 1);
    int c   = (idx >> 14) & (CPC - 1);
    int cam = idx >> 18;
    g_featsT[(((cam * HI + yh) * WI + xw) << 4) + c] = feats[idx];
}

// ---------------- kernel 3: bilinear grid sample into padded volume -------
__global__ void sample_kernel(const float* __restrict__ grids) {
    int tid = blockIdx.x * blockDim.x + threadIdx.x;   // 0 .. 4,194,304-1
    int x   = tid & (XD - 1);
    int y   = (tid >> 8) & (YD - 1);
    int z   = (tid >> 15) & (ZD - 1);
    int cam = tid >> 20;
    if (cam >= CAMN) return;

    float2 gv = ((const float2*)grids)[((cam * ZD + z) * YD + y) * XD + x];
    float ix = ((gv.x + 1.0f) * (float)WI - 1.0f) * 0.5f;
    float iy = ((gv.y + 1.0f) * (float)HI - 1.0f) * 0.5f;
    float x0f = floorf(ix), y0f = floorf(iy);
    float wx1 = ix - x0f, wx0 = 1.0f - wx1;
    float wy1 = iy - y0f, wy0 = 1.0f - wy1;
    int x0 = (int)x0f, y0 = (int)y0f;
    int x1 = x0 + 1,   y1 = y0 + 1;

    float a[CPC];
#pragma unroll
    for (int c = 0; c < CPC; c++) a[c] = 0.f;

    auto corner = [&](int xi, int yi, float w) {
        if (xi < 0 || xi > WI - 1 || yi < 0 || yi > HI - 1) return;
        const float4* p = (const float4*)(g_featsT + (((size_t)(cam * HI + yi) * WI + xi) << 4));
#pragma unroll
        for (int j = 0; j < 4; j++) {
            float4 v = p[j];
            a[4 * j + 0] = fmaf(w, v.x, a[4 * j + 0]);
            a[4 * j + 1] = fmaf(w, v.y, a[4 * j + 1]);
            a[4 * j + 2] = fmaf(w, v.z, a[4 * j + 2]);
            a[4 * j + 3] = fmaf(w, v.w, a[4 * j + 3]);
        }
    };
    corner(x0, y0, wx0 * wy0);
    corner(x1, y0, wx1 * wy0);
    corner(x0, y1, wx0 * wy1);
    corner(x1, y1, wx1 * wy1);

    size_t base = (((size_t)(cam * CPC) * PZ + (z + 1)) * PY + (y + 1)) * PX + (x + 1);
#pragma unroll
    for (int c = 0; c < CPC; c++)
        g_volp[base + (size_t)c * PLANE] = to_tf32(a[c]);
}

// ---------------- kernel 4: implicit-GEMM conv3d (tf32 mma.sync) ----------
// CTA: 64 oc x 128 x outputs at fixed (z,y). 256 threads = 8 warps (4 M x 2 N).
#define WS_STRIDE 68
#define VS_STRIDE 136
#define WS_FLOATS (3 * 64 * WS_STRIDE)   // 13056
#define VS_FLOATS (64 * VS_STRIDE)       // 8704
#define CONV_SMEM_BYTES ((WS_FLOATS + VS_FLOATS + 128) * 4)   // 87,552 B

__global__ void __launch_bounds__(256) conv_kernel(float* __restrict__ out,
                                                   const float* __restrict__ conv_b) {
    extern __shared__ float sh[];
    float* Ws   = sh;                         // [dx*64+oc][68]
    float* Vs   = sh + WS_FLOATS;             // [ic][136]
    float* sSum = sh + WS_FLOATS + VS_FLOATS; // [64]
    float* sSq  = sSum + 64;                  // [64]

    const int tid  = threadIdx.x;
    const int warp = tid >> 5, lane = tid & 31;
    const int wm = warp & 3;      // oc block (16 rows)
    const int wn = warp >> 2;     // x block (64 cols)
    const int r = lane >> 2, q = lane & 3;

    const int xt = blockIdx.x;    // 0..1
    const int yb = blockIdx.y;    // 0..127
    const int zb = blockIdx.z;    // 0..31
    const int x0 = xt * 128;

    if (tid < 64) { sSum[tid] = 0.f; sSq[tid] = 0.f; }

    float acc[8][4];
#pragma unroll
    for (int nt = 0; nt < 8; nt++)
#pragma unroll
        for (int j = 0; j < 4; j++) acc[nt][j] = 0.f;

    for (int dz = 0; dz < 3; dz++) {
        for (int dy = 0; dy < 3; dy++) {
            __syncthreads();
            // weights: 3*64*64 floats, coalesced float4, pad to stride 68
            const float4* wsrc = (const float4*)(g_wt + (size_t)((dz * 3 + dy) * 3) * 4096);
            for (int i4 = tid; i4 < 3072; i4 += 256) {
                float4 v = wsrc[i4];
                int j = i4 >> 4, c4 = i4 & 15;
                *(float4*)(Ws + j * WS_STRIDE + c4 * 4) = v;
            }
            // input strip: 64 ic x 130 x
            size_t vbase = ((size_t)(zb + dz) * PY + (yb + dy)) * PX + x0;
            for (int t = tid; t < 64 * 130; t += 256) {
                int icr = t / 130;
                int xx  = t - icr * 130;
                Vs[icr * VS_STRIDE + xx] = g_volp[(size_t)icr * PLANE + vbase + xx];
            }
            __syncthreads();

#pragma unroll
            for (int dx = 0; dx < 3; dx++) {
                const float* wbase = Ws + (dx * 64 + wm * 16 + r) * WS_STRIDE + q;
                const float* vcol  = Vs + q * VS_STRIDE + wn * 64 + r + dx;
#pragma unroll
                for (int k8 = 0; k8 < 8; k8++) {
                    const float* wr = wbase + k8 * 8;
                    uint32_t a0 = __float_as_uint(wr[0]);
                    uint32_t a1 = __float_as_uint(wr[8 * WS_STRIDE]);
                    uint32_t a2 = __float_as_uint(wr[4]);
                    uint32_t a3 = __float_as_uint(wr[8 * WS_STRIDE + 4]);
                    const float* vb = vcol + (k8 * 8) * VS_STRIDE;
#pragma unroll
                    for (int nt = 0; nt < 8; nt++) {
                        uint32_t b0 = __float_as_uint(vb[nt * 8]);
                        uint32_t b1 = __float_as_uint(vb[nt * 8 + 4 * VS_STRIDE]);
                        mma_tf32(acc[nt], a0, a1, a2, a3, b0, b1);
                    }
                }
            }
        }
    }

    // epilogue: bias add, store y to d_out, per-channel sum / sumsq
#pragma unroll
    for (int h = 0; h < 2; h++) {
        int ocl = wm * 16 + r + h * 8;
        float bias = conv_b[ocl];
        size_t obase = (((size_t)ocl * ZD + zb) * YD + yb) * XD;
        float s = 0.f, s2 = 0.f;
#pragma unroll
        for (int nt = 0; nt < 8; nt++) {
            float v0 = acc[nt][h * 2 + 0] + bias;
            float v1 = acc[nt][h * 2 + 1] + bias;
            int xg = x0 + wn * 64 + nt * 8 + q * 2;
            *(float2*)(out + obase + xg) = make_float2(v0, v1);
            s  += v0 + v1;
            s2 += v0 * v0 + v1 * v1;
        }
        s  += __shfl_xor_sync(0xffffffffu, s, 1);
        s  += __shfl_xor_sync(0xffffffffu, s, 2);
        s2 += __shfl_xor_sync(0xffffffffu, s2, 1);
        s2 += __shfl_xor_sync(0xffffffffu, s2, 2);
        if (q == 0) {
            atomicAdd(&sSum[ocl], s);
            atomicAdd(&sSq[ocl], s2);
        }
    }
    __syncthreads();
    if (tid < 64) {
        atomicAdd(&g_sum[tid], sSum[tid]);
        atomicAdd(&g_sq[tid], sSq[tid]);
    }
}

// ---------------- kernel 5: finalize BN scale/shift ------------------------
__global__ void finalize_kernel(const float* __restrict__ gamma,
                                const float* __restrict__ beta) {
    int c = threadIdx.x;
    if (c >= FC) return;
    const float n = (float)NC_ELEMS;
    float mean = g_sum[c] / n;
    float var  = g_sq[c] / n - mean * mean;
    float sc = gamma[c] * rsqrtf(var + EPSBN);
    g_scale[c] = sc;
    g_shift[c] = beta[c] - mean * sc;
}

// ---------------- kernel 6: in-place BN + leaky relu -----------------------
__global__ void bnlrelu_kernel(float* __restrict__ out) {
    int i4 = blockIdx.x * blockDim.x + threadIdx.x;    // 0 .. 16,777,216-1
    int oc = i4 >> 18;                                 // 262,144 float4 per channel
    float sc = g_scale[oc], shv = g_shift[oc];
    float4 v = ((float4*)out)[i4];
    float t;
    t = v.x * sc + shv; v.x = t > 0.f ? t : 0.01f * t;
    t = v.y * sc + shv; v.y = t > 0.f ? t : 0.01f * t;
    t = v.z * sc + shv; v.z = t > 0.f ? t : 0.01f * t;
    t = v.w * sc + shv; v.w = t > 0.f ? t : 0.01f * t;
    ((float4*)out)[i4] = v;
}

// ---------------- launch ----------------------------------------------------
extern "C" void kernel_launch(void* const* d_in, const int* in_sizes, int n_in,
                              void* d_out, int out_size) {
    const float* feats  = (const float*)d_in[0];
    const float* grids  = (const float*)d_in[1];
    // d_in[2] grid_masks, d_in[3] masks: unused by reference
    const float* conv_w = (const float*)d_in[4];
    const float* conv_b = (const float*)d_in[5];
    const float* gamma  = (const float*)d_in[6];
    const float* beta   = (const float*)d_in[7];
    float* out = (float*)d_out;

    cudaFuncSetAttribute(conv_kernel, cudaFuncAttributeMaxDynamicSharedMemorySize,
                         CONV_SMEM_BYTES);

    prep_kernel<<<432, 256>>>(conv_w);            // 27*4096 = 110,592
    transpose_kernel<<<4096, 256>>>(feats);       // 1,048,576
    sample_kernel<<<16384, 256>>>(grids);         // 4,194,304
    conv_kernel<<<dim3(2, YD, ZD), 256, CONV_SMEM_BYTES>>>(out, conv_b);
    finalize_kernel<<<1, 64>>>(gamma, beta);
    bnlrelu_kernel<<<65536, 256>>>(out);          // 16,777,216 float4
}

// round 5
// speedup vs baseline: 2.9309x; 2.9309x over previous
#include <cuda_runtime.h>
#include <cuda_fp16.h>
#include <cstdint>

// ---------------- problem constants ----------------
#define CAMN  4
#define CPC   16
#define FC    64
#define HI    128
#define WI    128
#define ZD    32
#define YD    128
#define XD    256
#define PZ    34
#define PY    130
#define PX    258
#define NC_ELEMS (ZD * YD * XD)
#define EPSBN 1e-5f

// ---------------- device scratch (zero-init; halo stays 0) ------------------
__device__ __half g_volh[(size_t)PZ * PY * PX * FC];   // [pz][py][px][ic] fp16 ~146MB
__device__ __half g_feath[CAMN * HI * WI * CPC];       // [cam][y][x][c] fp16
__device__ __half g_wh[27 * FC * FC];                  // [koff][oc][ic] fp16, koff=dz*9+dy*3+dx
__device__ float  g_sum[FC], g_sq[FC], g_scale[FC], g_shift[FC];

// ---------------- ptx helpers ----------------
__device__ __forceinline__ uint32_t smem_u32(const void* p) {
    uint32_t a;
    asm("{ .reg .u64 t; cvta.to.shared.u64 t, %1; cvt.u32.u64 %0, t; }" : "=r"(a) : "l"(p));
    return a;
}
__device__ __forceinline__ void cpasync16(uint32_t dst, const void* src) {
    asm volatile("cp.async.cg.shared.global [%0], [%1], 16;" :: "r"(dst), "l"(src));
}
#define CP_COMMIT() asm volatile("cp.async.commit_group;" ::: "memory")
#define CP_WAIT1()  asm volatile("cp.async.wait_group 1;" ::: "memory")
#define CP_WAIT0()  asm volatile("cp.async.wait_group 0;" ::: "memory")

#define LDSM_X4(r, a)                                                              \
    asm volatile("ldmatrix.sync.aligned.m8n8.x4.shared.b16 {%0,%1,%2,%3}, [%4];"   \
        : "=r"((r)[0]), "=r"((r)[1]), "=r"((r)[2]), "=r"((r)[3]) : "r"(a))

#define MMA16816(c, a, b0, b1)                                                     \
    asm volatile("mma.sync.aligned.m16n8k16.row.col.f32.f16.f16.f32 "              \
        "{%0,%1,%2,%3},{%4,%5,%6,%7},{%8,%9},{%0,%1,%2,%3};"                       \
        : "+f"((c)[0]), "+f"((c)[1]), "+f"((c)[2]), "+f"((c)[3])                    \
        : "r"((a)[0]), "r"((a)[1]), "r"((a)[2]), "r"((a)[3]), "r"(b0), "r"(b1))

// ---------------- kernel 1: weights -> fp16 [koff][oc][ic], zero stats ------
__global__ void prep_kernel(const float* __restrict__ conv_w) {
    int idx = blockIdx.x * blockDim.x + threadIdx.x;
    if (idx < FC) { g_sum[idx] = 0.f; g_sq[idx] = 0.f; }
    if (idx >= 27 * FC * FC) return;
    int koff = idx >> 12, rem = idx & 4095;
    int oc = rem >> 6, ic = rem & 63;
    g_wh[idx] = __float2half(conv_w[(oc * 64 + ic) * 27 + koff]);
}

// ---------------- kernel 2: feats transpose -> fp16 [cam][y][x][c] ----------
__global__ void transpose_kernel(const float* __restrict__ feats) {
    int idx = blockIdx.x * blockDim.x + threadIdx.x;
    if (idx >= CAMN * CPC * HI * WI) return;
    int xw = idx & (WI - 1);
    int yh = (idx >> 7) & (HI - 1);
    int c  = (idx >> 14) & (CPC - 1);
    int cam = idx >> 18;
    g_feath[(((cam * HI + yh) * WI + xw) << 4) + c] = __float2half(feats[idx]);
}

// ---------------- kernel 3: bilinear sample -> fp16 padded volume -----------
__global__ void sample_kernel(const float* __restrict__ grids) {
    int tid = blockIdx.x * blockDim.x + threadIdx.x;
    int x = tid & (XD - 1);
    int y = (tid >> 8) & (YD - 1);
    int z = (tid >> 15) & (ZD - 1);
    int cam = tid >> 20;
    if (cam >= CAMN) return;

    float2 gv = ((const float2*)grids)[((cam * ZD + z) * YD + y) * XD + x];
    float ix = ((gv.x + 1.0f) * (float)WI - 1.0f) * 0.5f;
    float iy = ((gv.y + 1.0f) * (float)HI - 1.0f) * 0.5f;
    float x0f = floorf(ix), y0f = floorf(iy);
    float wx1 = ix - x0f, wx0 = 1.0f - wx1;
    float wy1 = iy - y0f, wy0 = 1.0f - wy1;
    int x0 = (int)x0f, y0 = (int)y0f;
    int x1 = x0 + 1, y1 = y0 + 1;

    float a[CPC];
#pragma unroll
    for (int c = 0; c < CPC; c++) a[c] = 0.f;
    auto corner = [&](int xi, int yi, float w) {
        if (xi < 0 || xi > WI - 1 || yi < 0 || yi > HI - 1) return;
        const uint4* p = (const uint4*)(g_feath + ((size_t)((cam * HI + yi) * WI + xi) << 4));
        uint4 u0 = p[0], u1 = p[1];
        const __half2* h0 = (const __half2*)&u0;
        const __half2* h1 = (const __half2*)&u1;
#pragma unroll
        for (int j = 0; j < 4; j++) {
            float2 f0 = __half22float2(h0[j]);
            a[2*j]   = fmaf(w, f0.x, a[2*j]);
            a[2*j+1] = fmaf(w, f0.y, a[2*j+1]);
            float2 f1 = __half22float2(h1[j]);
            a[8+2*j] = fmaf(w, f1.x, a[8+2*j]);
            a[9+2*j] = fmaf(w, f1.y, a[9+2*j]);
        }
    };
    corner(x0, y0, wx0 * wy0);
    corner(x1, y0, wx1 * wy0);
    corner(x0, y1, wx0 * wy1);
    corner(x1, y1, wx1 * wy1);

    __half2 hv[8];
#pragma unroll
    for (int j = 0; j < 8; j++) hv[j] = __floats2half2_rn(a[2*j], a[2*j+1]);
    size_t base = ((((size_t)(z + 1) * PY + (y + 1)) * PX + (x + 1)) << 6) + cam * 16;
    uint4* dst = (uint4*)(g_volh + base);
    dst[0] = *(uint4*)&hv[0];
    dst[1] = *(uint4*)&hv[4];
}

// ---------------- kernel 4: fp16 mma.sync implicit-GEMM conv3d --------------
// CTA: M=128 x-outputs x N=64 oc at fixed (z,y). 8 warps: 4(M)x2(N), warp tile
// 32x32. K = 27 slices of 64 ic, staged (dy,dz) with cp.async double buffering;
// dx folded via shifted ldmatrix row addressing on the 130-row A strip.
#define AS_BYTES 16640                  // 130 rows * 128B
#define BS_BYTES 24576                  // 3 dx * 64 oc * 128B
#define STG_BYTES (AS_BYTES + BS_BYTES) // 41216
#define CONV_SMEM (2 * STG_BYTES)       // 82432

__global__ void __launch_bounds__(256, 2) conv_kernel(float* __restrict__ out,
                                                      const float* __restrict__ conv_b) {
    extern __shared__ char sh[];
    const uint32_t sbase = smem_u32(sh);
    const int tid = threadIdx.x, lane = tid & 31, wid = tid >> 5;
    const int wm = wid & 3, wn = wid >> 2;
    const int x0 = blockIdx.x << 7;    // 0 or 128
    const int y  = blockIdx.y;
    const int z  = blockIdx.z;

    auto fill = [&](int s, uint32_t bb) {
        const int dy = s / 3, dz = s - dy * 3;
        const char* asrc = (const char*)(g_volh +
            ((((size_t)(z + dz)) * PY + (y + dy)) * PX + x0) * 64);
        for (int i = tid; i < 1040; i += 256) {           // 130 rows x 8 chunks
            int r = i >> 3, c = i & 7;
            cpasync16(bb + r * 128 + ((c ^ (r & 7)) << 4), asrc + i * 16);
        }
        const char* bsrc = (const char*)(g_wh + (size_t)(dz * 9 + dy * 3) * 4096);
        for (int i = tid; i < 1536; i += 256) {           // 192 rows x 8 chunks
            int r = i >> 3, c = i & 7;
            cpasync16(bb + AS_BYTES + r * 128 + ((c ^ (r & 7)) << 4), bsrc + i * 16);
        }
    };

    float acc[2][4][4];
#pragma unroll
    for (int mi = 0; mi < 2; mi++)
#pragma unroll
        for (int nj = 0; nj < 4; nj++)
#pragma unroll
            for (int k = 0; k < 4; k++) acc[mi][nj][k] = 0.f;

    // per-lane ldmatrix address components
    const int lane_r  = lane & 15;             // A: row within 16
    const int lane_ca = lane >> 4;             // A: k-chunk select
    const int lane_n  = (lane & 7) | ((lane & 16) >> 1);   // B: n row
    const int lane_cb = (lane >> 3) & 1;       // B: k-chunk select

    fill(0, sbase); CP_COMMIT();
    for (int s = 0; s < 9; s++) {
        if (s < 8) { fill(s + 1, sbase + ((s + 1) & 1) * STG_BYTES); CP_COMMIT(); CP_WAIT1(); }
        else       { CP_WAIT0(); }
        __syncthreads();
        const uint32_t ab = sbase + (s & 1) * STG_BYTES;
        const uint32_t bb = ab + AS_BYTES;
#pragma unroll
        for (int dx = 0; dx < 3; dx++) {
#pragma unroll
            for (int kk = 0; kk < 4; kk++) {
                uint32_t a[2][4], b[2][4];
#pragma unroll
                for (int mi = 0; mi < 2; mi++) {
                    int row = wm * 32 + mi * 16 + lane_r + dx;
                    LDSM_X4(a[mi], ab + row * 128 + (((kk * 2 + lane_ca) ^ (row & 7)) << 4));
                }
#pragma unroll
                for (int nb = 0; nb < 2; nb++) {
                    int nr = wn * 32 + nb * 16 + lane_n;
                    LDSM_X4(b[nb], bb + dx * 8192 + nr * 128 +
                                   (((kk * 2 + lane_cb) ^ (nr & 7)) << 4));
                }
#pragma unroll
                for (int mi = 0; mi < 2; mi++)
#pragma unroll
                    for (int nj = 0; nj < 4; nj++)
                        MMA16816(acc[mi][nj], a[mi],
                                 b[nj >> 1][(nj & 1) * 2], b[nj >> 1][(nj & 1) * 2 + 1]);
            }
        }
        __syncthreads();
    }

    // epilogue: bias + store (C frag: c0,c1 = row g cols 2t,2t+1; c2,c3 = row g+8)
    const int g = lane >> 2, t = lane & 3;
    const size_t zy = ((size_t)z * YD + y) * XD;
#pragma unroll
    for (int mi = 0; mi < 2; mi++) {
        const int xr = x0 + wm * 32 + mi * 16 + g;
#pragma unroll
        for (int nj = 0; nj < 4; nj++) {
            const int oc = wn * 32 + nj * 8 + 2 * t;
            const float b0v = __ldg(&conv_b[oc]), b1v = __ldg(&conv_b[oc + 1]);
            out[(size_t)oc * NC_ELEMS + zy + xr]           = acc[mi][nj][0] + b0v;
            out[(size_t)(oc + 1) * NC_ELEMS + zy + xr]     = acc[mi][nj][1] + b1v;
            out[(size_t)oc * NC_ELEMS + zy + xr + 8]       = acc[mi][nj][2] + b0v;
            out[(size_t)(oc + 1) * NC_ELEMS + zy + xr + 8] = acc[mi][nj][3] + b1v;
        }
    }
}

// ---------------- kernel 5: per-channel stats over conv output --------------
__global__ void stats_kernel(const float* __restrict__ out) {
    int oc = blockIdx.x >> 3, seg = blockIdx.x & 7;
    const float4* p = (const float4*)(out + (size_t)oc * NC_ELEMS) + (size_t)seg * 32768;
    float s = 0.f, s2 = 0.f;
    for (int i = threadIdx.x; i < 32768; i += 256) {
        float4 v = p[i];
        s  += v.x + v.y + v.z + v.w;
        s2 += v.x * v.x + v.y * v.y + v.z * v.z + v.w * v.w;
    }
#pragma unroll
    for (int o = 16; o; o >>= 1) {
        s  += __shfl_down_sync(0xffffffffu, s, o);
        s2 += __shfl_down_sync(0xffffffffu, s2, o);
    }
    __shared__ float as[8], aq[8];
    if ((threadIdx.x & 31) == 0) { as[threadIdx.x >> 5] = s; aq[threadIdx.x >> 5] = s2; }
    __syncthreads();
    if (threadIdx.x < 8) {
        s = as[threadIdx.x]; s2 = aq[threadIdx.x];
#pragma unroll
        for (int o = 4; o; o >>= 1) {
            s  += __shfl_down_sync(0xffu, s, o);
            s2 += __shfl_down_sync(0xffu, s2, o);
        }
        if (threadIdx.x == 0) { atomicAdd(&g_sum[oc], s); atomicAdd(&g_sq[oc], s2); }
    }
}

// ---------------- kernel 6: finalize BN scale/shift -------------------------
__global__ void finalize_kernel(const float* __restrict__ gamma,
                                const float* __restrict__ beta) {
    int c = threadIdx.x;
    if (c >= FC) return;
    const float n = (float)NC_ELEMS;
    float mean = g_sum[c] / n;
    float var  = g_sq[c] / n - mean * mean;
    float sc = gamma[c] * rsqrtf(var + EPSBN);
    g_scale[c] = sc;
    g_shift[c] = beta[c] - mean * sc;
}

// ---------------- kernel 7: in-place BN + leaky relu ------------------------
__global__ void bnlrelu_kernel(float* __restrict__ out) {
    int i4 = blockIdx.x * blockDim.x + threadIdx.x;
    int oc = i4 >> 18;
    float sc = g_scale[oc], shv = g_shift[oc];
    float4 v = ((float4*)out)[i4];
    float t;
    t = v.x * sc + shv; v.x = t > 0.f ? t : 0.01f * t;
    t = v.y * sc + shv; v.y = t > 0.f ? t : 0.01f * t;
    t = v.z * sc + shv; v.z = t > 0.f ? t : 0.01f * t;
    t = v.w * sc + shv; v.w = t > 0.f ? t : 0.01f * t;
    ((float4*)out)[i4] = v;
}

// ---------------- launch ----------------------------------------------------
extern "C" void kernel_launch(void* const* d_in, const int* in_sizes, int n_in,
                              void* d_out, int out_size) {
    const float* feats  = (const float*)d_in[0];
    const float* grids  = (const float*)d_in[1];
    const float* conv_w = (const float*)d_in[4];
    const float* conv_b = (const float*)d_in[5];
    const float* gamma  = (const float*)d_in[6];
    const float* beta   = (const float*)d_in[7];
    float* out = (float*)d_out;

    cudaFuncSetAttribute(conv_kernel, cudaFuncAttributeMaxDynamicSharedMemorySize, CONV_SMEM);

    prep_kernel<<<432, 256>>>(conv_w);
    transpose_kernel<<<4096, 256>>>(feats);
    sample_kernel<<<16384, 256>>>(grids);
    conv_kernel<<<dim3(2, 128, 32), 256, CONV_SMEM>>>(out, conv_b);
    stats_kernel<<<512, 256>>>(out);
    finalize_kernel<<<1, 64>>>(gamma, beta);
    bnlrelu_kernel<<<65536, 256>>>(out);
}